// round 15
// baseline (speedup 1.0000x reference)
#include <cuda_runtime.h>
#include <cuda_fp16.h>
#include <math.h>

#define BB 64      // batch
#define TT 512     // decode steps
#define TE 1024    // encoder steps
#define EE 512     // encoder dim
#define UU 256     // units
#define NC 64      // classes
#define GG 1024    // 4*U gates
#define VV 1024    // U (x) + E (ctx) + U (h)

#define STAGE_BYTES 49152          // enc 16 KB + speech 32 KB
#define RED_OFF     98304          // red area after the two stages
#define DSM_BYTES   102400         // 96 KB stages + 4 KB red

// ---------------- scratch (static device globals; no allocation) -------------
__device__ float d_secrets[BB * TT * UU];
__device__ __half d_enc1h[BB * TE * UU];   // fp16 enc, layer1
__device__ __half d_enc2h[BB * TE * UU];   // fp16 enc, layer2
__device__ __half d_speechh[BB * TE * EE]; // fp16 speech
__device__ float d_o1[BB * TT * UU];
__device__ float d_o2[BB * TT * UU];
__device__ float d_m1o[BB * TT * UU];
__device__ float d_m2o[BB * TT * UU];
__device__ float d_lg[BB * TT * NC];
__device__ float d_vT[2 * VV * BB];      // [layer][row 0..1023][batch]  (transposed v)
__device__ float d_Z[2 * BB * GG];       // [layer][batch][gate]
__device__ unsigned d_bar[128];          // grid-barrier flags (monotone)

__device__ __forceinline__ float tanh_fast(float x) {
    float y;
    asm("tanh.approx.f32 %0, %1;" : "=f"(y) : "f"(x));
    return y;
}

__device__ __forceinline__ void cp16(unsigned saddr, const void* g) {
    asm volatile("cp.async.cg.shared.global [%0], [%1], 16;"
                 :: "r"(saddr), "l"(g));
}

// -------- grid barrier: release/acquire flags, monotone phase ---------------
__device__ __forceinline__ void gbar(unsigned& ph) {
    __threadfence();
    __syncthreads();
    ph++;
    if (threadIdx.x == 0) {
        asm volatile("st.release.gpu.global.u32 [%0], %1;"
                     :: "l"(&d_bar[blockIdx.x]), "r"(ph) : "memory");
    }
    if (threadIdx.x < 128) {
        unsigned v;
        do {
            asm volatile("ld.acquire.gpu.global.u32 %0, [%1];"
                         : "=r"(v) : "l"(&d_bar[threadIdx.x]) : "memory");
        } while ((int)(v - ph) < 0);
    }
    __syncthreads();
    __threadfence();
}

// ---------------------------------------------------------------------------
// Persistent decoder: both attention-LSTM layers, pipelined (layer2 one step
// behind layer1). grid = 128 CTAs (L = bid/64, b = bid%64), block = 512.
// Fused attention streams te in 32-row blocks staged via cp.async (double
// buffer), online softmax + ctx per warp, exact 16-way merge.
// ---------------------------------------------------------------------------
__global__ __launch_bounds__(512, 1) void decoder_persistent(
    const float* __restrict__ Wa1W, const float* __restrict__ Wa1b,
    const float* __restrict__ va1W, const float* __restrict__ va1b,
    const float* __restrict__ K1, const float* __restrict__ R1, const float* __restrict__ b1,
    const float* __restrict__ Wa2W, const float* __restrict__ Wa2b,
    const float* __restrict__ va2W, const float* __restrict__ va2b,
    const float* __restrict__ K2, const float* __restrict__ R2, const float* __restrict__ b2)
{
    extern __shared__ __align__(16) char dsm[];

    const int bid = blockIdx.x;
    const int tid = threadIdx.x;
    const int L = bid >> 6;         // 0 = layer1, 1 = layer2
    const int b = bid & 63;
    const int lane = tid & 31, warp = tid >> 5;   // 16 warps

    const __half* ench = L ? d_enc2h : d_enc1h;
    const float* WaW = L ? Wa2W : Wa1W;
    const float* Wab = L ? Wa2b : Wa1b;
    const float* vaW = L ? va2W : va1W;
    const float* Kw  = L ? K2 : K1;
    const float* Rw  = L ? R2 : R1;
    const float* bz  = L ? b2 : b1;
    float* outbuf = L ? d_o2 : d_o1;
    float* vT = d_vT + L * (VV * BB);
    float* Zl = d_Z + L * (BB * GG);

    const char* encG = (const char*)(ench + (size_t)b * TE * UU);        // 512 B rows
    const char* spG  = (const char*)(d_speechh + (size_t)b * TE * EE);   // 1024 B rows
    const unsigned smemBase = (unsigned)__cvta_generic_to_shared(dsm);

    __shared__ float sh_h[UU];
    __shared__ float sh_s[UU];
    __shared__ float sm_m[16], sm_s[16];
    float* red = (float*)(dsm + RED_OFF);      // 1024 floats

    float c_reg = 0.0f;            // cell state (threads 0..255)
    unsigned ph = *((volatile unsigned*)&d_bar[bid]);

    for (int k = 0; k <= 513; k++) {
        const int t = k - L;                    // this layer's step
        const bool attnAct = (t >= 0) && (t < TT);
        const bool gateAct = (t >= 1) && (t <= TT);

        if (k) gbar(ph);   // B0: Z of previous iteration complete

        // ---- prologue: stage te-block 0 (latency hidden by phases A/1) ----
        if (attnAct) {
            const unsigned st = smemBase;          // stage 0
            cp16(st + tid * 16,              encG + tid * 16);
            cp16(st + (tid + 512) * 16,      encG + (tid + 512) * 16);
            const unsigned sd = st + 16384;
#pragma unroll
            for (int i = 0; i < 4; i++)
                cp16(sd + (tid + 512 * i) * 16, spG + (size_t)(tid + 512 * i) * 16);
            asm volatile("cp.async.commit_group;");
        }

        // ---------------- phase A: gates -> h_{t-1} ------------------------
        if (tid < UU) {
            if (gateAct) {
                const float* Zb = Zl + b * GG;
                float zi = bz[tid]       + __ldcg(Zb + tid);
                float zf = bz[tid + 256] + __ldcg(Zb + tid + 256);
                float zg = bz[tid + 512] + __ldcg(Zb + tid + 512);
                float zo = bz[tid + 768] + __ldcg(Zb + tid + 768);
                float ig = 1.0f / (1.0f + expf(-zi));
                float fg = 1.0f / (1.0f + expf(-zf));
                float og = 1.0f / (1.0f + expf(-zo));
                c_reg = fg * c_reg + ig * tanhf(zg);
                float h = og * tanhf(c_reg);
                sh_h[tid] = h;
                __stcg(vT + (768 + tid) * BB + b, h);
                __stcg(outbuf + ((size_t)b * TT + (t - 1)) * UU + tid, h);
            } else if (attnAct) {   // t == 0 init
                c_reg = 0.0f;
                sh_h[tid] = 0.0f;
                __stcg(vT + (768 + tid) * BB + b, 0.0f);
            }
        }

        gbar(ph);          // B1: h / o1 rows visible grid-wide

        if (attnAct) {
            // ---- x_t (layer2: norm of layer1's h_t, written this iter) ----
            float xv = 0.0f;
            if (tid < UU) {
                xv = (L == 0) ? d_secrets[((size_t)b * TT + t) * UU + tid]
                              : __ldcg(d_o1 + ((size_t)b * TT + t) * UU + tid);
            }
            if (L == 1) {   // uniform per CTA -> syncthreads legal
                red[tid]       = (tid < UU) ? xv : 0.0f;
                red[512 + tid] = (tid < UU) ? xv * xv : 0.0f;
                __syncthreads();
                for (int o = 256; o > 0; o >>= 1) {
                    if (tid < o) {
                        red[tid] += red[tid + o];
                        red[512 + tid] += red[512 + tid + o];
                    }
                    __syncthreads();
                }
                const float mean = red[0] * (1.0f / 256.0f);
                const float var  = red[512] * (1.0f / 256.0f) - mean * mean;
                const float sc = rsqrtf(var + 1e-4f);
                xv = (xv - mean) * sc;
                __syncthreads();
            }
            if (tid < UU) __stcg(vT + tid * BB + b, xv);

            // ---- phase 1: s = h @ Wa + Wa_b -------------------------------
            {
                const int uu = tid & 255, half = tid >> 8;
                float acc = 0.0f;
                const float* wp = WaW + (size_t)(half * 128) * UU + uu;
#pragma unroll 8
                for (int kk = 0; kk < 128; kk++)
                    acc += sh_h[half * 128 + kk] * wp[(size_t)kk * UU];
                red[tid] = acc;
                __syncthreads();
                if (tid < UU) sh_s[tid] = red[tid] + red[tid + 256] + Wab[tid];
                __syncthreads();
            }

            // ---- FUSED phases 2-4: staged online softmax + ctx ------------
            {
                float va_r[8], s_r[8];
#pragma unroll
                for (int j = 0; j < 8; j++) {
                    va_r[j] = vaW[lane * 8 + j];
                    s_r[j]  = sh_s[lane * 8 + j];
                }

                float m = -1e30f, s = 0.0f;
                float acc[16];
#pragma unroll
                for (int i = 0; i < 16; i++) acc[i] = 0.0f;

                const int r0 = warp * 2, r1 = r0 + 1;

#pragma unroll 1
                for (int blk = 0; blk < 32; blk++) {
                    const int cur = blk & 1;
                    // stage next block, then wait for current
                    if (blk < 31) {
                        const unsigned st = smemBase + (cur ^ 1) * STAGE_BYTES;
                        const char* eS = encG + (size_t)(blk + 1) * 16384;
                        const char* sS = spG  + (size_t)(blk + 1) * 32768;
                        cp16(st + tid * 16,         eS + tid * 16);
                        cp16(st + (tid + 512) * 16, eS + (tid + 512) * 16);
                        const unsigned sd = st + 16384;
#pragma unroll
                        for (int i = 0; i < 4; i++)
                            cp16(sd + (tid + 512 * i) * 16,
                                 sS + (size_t)(tid + 512 * i) * 16);
                        asm volatile("cp.async.commit_group;");
                        asm volatile("cp.async.wait_group 1;");
                    } else {
                        asm volatile("cp.async.wait_group 0;");
                    }
                    __syncthreads();

                    const uint4* eP = (const uint4*)(dsm + cur * STAGE_BYTES);
                    const uint4* sP = (const uint4*)(dsm + cur * STAGE_BYTES + 16384);
                    uint4 e0  = eP[r0 * 32 + lane];
                    uint4 e1  = eP[r1 * 32 + lane];
                    uint4 sA0 = sP[r0 * 64 + lane];
                    uint4 sB0 = sP[r0 * 64 + 32 + lane];
                    uint4 sA1 = sP[r1 * 64 + lane];
                    uint4 sB1 = sP[r1 * 64 + 32 + lane];

                    float l0 = 0.f, l1 = 0.f;
                    {
                        const __half2* h0 = reinterpret_cast<const __half2*>(&e0);
                        const __half2* h1 = reinterpret_cast<const __half2*>(&e1);
#pragma unroll
                        for (int pp = 0; pp < 4; pp++) {
                            float2 f0 = __half22float2(h0[pp]);
                            float2 f1 = __half22float2(h1[pp]);
                            l0 += va_r[2 * pp]     * tanh_fast(s_r[2 * pp]     + f0.x);
                            l1 += va_r[2 * pp]     * tanh_fast(s_r[2 * pp]     + f1.x);
                            l0 += va_r[2 * pp + 1] * tanh_fast(s_r[2 * pp + 1] + f0.y);
                            l1 += va_r[2 * pp + 1] * tanh_fast(s_r[2 * pp + 1] + f1.y);
                        }
                    }
#pragma unroll
                    for (int o = 16; o; o >>= 1) {
                        l0 += __shfl_xor_sync(0xffffffffu, l0, o);
                        l1 += __shfl_xor_sync(0xffffffffu, l1, o);
                    }

                    // row r0 (warp-uniform branch)
                    if (l0 > m) {
                        const float corr = __expf(m - l0);
                        m = l0;
                        s *= corr;
#pragma unroll
                        for (int i = 0; i < 16; i++) acc[i] *= corr;
                    }
                    {
                        const float w = __expf(l0 - m);
                        s += w;
                        const __half2* hA = reinterpret_cast<const __half2*>(&sA0);
                        const __half2* hB = reinterpret_cast<const __half2*>(&sB0);
#pragma unroll
                        for (int pp = 0; pp < 4; pp++) {
                            float2 fa = __half22float2(hA[pp]);
                            float2 fb = __half22float2(hB[pp]);
                            acc[2 * pp]         += w * fa.x;
                            acc[2 * pp + 1]     += w * fa.y;
                            acc[8 + 2 * pp]     += w * fb.x;
                            acc[8 + 2 * pp + 1] += w * fb.y;
                        }
                    }
                    // row r1
                    if (l1 > m) {
                        const float corr = __expf(m - l1);
                        m = l1;
                        s *= corr;
#pragma unroll
                        for (int i = 0; i < 16; i++) acc[i] *= corr;
                    }
                    {
                        const float w = __expf(l1 - m);
                        s += w;
                        const __half2* hA = reinterpret_cast<const __half2*>(&sA1);
                        const __half2* hB = reinterpret_cast<const __half2*>(&sB1);
#pragma unroll
                        for (int pp = 0; pp < 4; pp++) {
                            float2 fa = __half22float2(hA[pp]);
                            float2 fb = __half22float2(hB[pp]);
                            acc[2 * pp]         += w * fa.x;
                            acc[2 * pp + 1]     += w * fa.y;
                            acc[8 + 2 * pp]     += w * fb.x;
                            acc[8 + 2 * pp + 1] += w * fb.y;
                        }
                    }
                    __syncthreads();   // done reading stage cur before refill
                }

                // ---- exact 16-way flash merge across warps ----------------
                if (lane == 0) { sm_m[warp] = m; sm_s[warp] = s; }
                __syncthreads();
                float M = sm_m[0];
#pragma unroll
                for (int w2 = 1; w2 < 16; w2++) M = fmaxf(M, sm_m[w2]);
                float S = 0.0f;
#pragma unroll
                for (int w2 = 0; w2 < 16; w2++)
                    S += sm_s[w2] * __expf(sm_m[w2] - M);
                const float fw = __expf(m - M);
                const float invS = 1.0f / S;
                float* buf = (float*)dsm;      // [16][512]
                {
                    float4 v0 = make_float4(acc[0] * fw, acc[1] * fw,
                                            acc[2] * fw, acc[3] * fw);
                    float4 v1 = make_float4(acc[4] * fw, acc[5] * fw,
                                            acc[6] * fw, acc[7] * fw);
                    float4 v2 = make_float4(acc[8] * fw, acc[9] * fw,
                                            acc[10] * fw, acc[11] * fw);
                    float4 v3 = make_float4(acc[12] * fw, acc[13] * fw,
                                            acc[14] * fw, acc[15] * fw);
                    float4* bp = reinterpret_cast<float4*>(buf + warp * 512);
                    bp[lane * 2]           = v0;
                    bp[lane * 2 + 1]       = v1;
                    bp[64 + lane * 2]      = v2;
                    bp[64 + lane * 2 + 1]  = v3;
                }
                __syncthreads();
                float ctx = 0.0f;
#pragma unroll
                for (int w2 = 0; w2 < 16; w2++)
                    ctx += buf[w2 * 512 + tid];
                __stcg(vT + (256 + tid) * BB + b, ctx * invS);
            }
        }

        gbar(ph);          // B2: v (all batches, this layer) visible

        // ---------------- phase D: Z[:, 16 cols] = v @ [K;R] ----------------
        if (attnAct) {
            float (*vsh)[68] = reinterpret_cast<float(*)[68]>((float*)dsm);
            float (*wsh)[20] = reinterpret_cast<float(*)[20]>((float*)dsm + 64 * 68);
            const int c0 = b * 16;
            const int rg = tid & 7, cg = (tid >> 3) & 3, bg = tid >> 5;
            float acc[4][4] = {};

            for (int tile = 0; tile < 16; tile++) {
                const int rbase = tile * 64;
#pragma unroll
                for (int i = 0; i < 2; i++) {
                    const int e4i = i * 512 + tid;
                    const int r = e4i >> 4, b4 = e4i & 15;
                    float4 vv = __ldcg(
                        reinterpret_cast<const float4*>(vT + (size_t)(rbase + r) * BB) + b4);
                    *reinterpret_cast<float4*>(&vsh[r][b4 * 4]) = vv;
                }
                if (tid < 256) {
                    const int r = tid >> 2, c4 = tid & 3;
                    const int gr = rbase + r;
                    const float* Wrow = (gr < 768) ? (Kw + (size_t)gr * GG)
                                                   : (Rw + (size_t)(gr - 768) * GG);
                    *reinterpret_cast<float4*>(&wsh[r][c4 * 4]) =
                        *reinterpret_cast<const float4*>(Wrow + c0 + c4 * 4);
                }
                __syncthreads();
#pragma unroll
                for (int rr = 0; rr < 8; rr++) {
                    const int r = rr * 8 + rg;
                    float4 vv = *reinterpret_cast<const float4*>(&vsh[r][bg * 4]);
                    float4 ww = *reinterpret_cast<const float4*>(&wsh[r][cg * 4]);
                    const float vvv[4] = {vv.x, vv.y, vv.z, vv.w};
                    const float www[4] = {ww.x, ww.y, ww.z, ww.w};
#pragma unroll
                    for (int i = 0; i < 4; i++)
#pragma unroll
                        for (int j = 0; j < 4; j++)
                            acc[i][j] += vvv[i] * www[j];
                }
                __syncthreads();
            }
            // reduce over rg (lane bits 0..2)
#pragma unroll
            for (int i = 0; i < 4; i++)
#pragma unroll
                for (int j = 0; j < 4; j++) {
                    float a = acc[i][j];
                    a += __shfl_xor_sync(0xffffffffu, a, 1);
                    a += __shfl_xor_sync(0xffffffffu, a, 2);
                    a += __shfl_xor_sync(0xffffffffu, a, 4);
                    acc[i][j] = a;
                }
            if (rg == 0) {
#pragma unroll
                for (int i = 0; i < 4; i++)
#pragma unroll
                    for (int j = 0; j < 4; j++)
                        __stcg(Zl + (size_t)(bg * 4 + i) * GG + c0 + cg * 4 + j, acc[i][j]);
            }
        }
    }
}

// ---------------------------------------------------------------------------
// fp32 -> fp16 bulk convert, 8 elems/thread.
// ---------------------------------------------------------------------------
__global__ __launch_bounds__(256) void f2h_kernel(
    const float* __restrict__ in, __half* __restrict__ out, int n8)
{
    const int i = blockIdx.x * blockDim.x + threadIdx.x;
    if (i >= n8) return;
    const float4* p = reinterpret_cast<const float4*>(in) + 2 * i;
    float4 a = p[0], c = p[1];
    __half2 h0 = __floats2half2_rn(a.x, a.y);
    __half2 h1 = __floats2half2_rn(a.z, a.w);
    __half2 h2 = __floats2half2_rn(c.x, c.y);
    __half2 h3 = __floats2half2_rn(c.z, c.w);
    uint4 q;
    q.x = *reinterpret_cast<unsigned*>(&h0);
    q.y = *reinterpret_cast<unsigned*>(&h1);
    q.z = *reinterpret_cast<unsigned*>(&h2);
    q.w = *reinterpret_cast<unsigned*>(&h3);
    reinterpret_cast<uint4*>(out)[i] = q;
}

// ---------------------------------------------------------------------------
// Generic tiled SGEMM: C[M,N] = A[M,K] @ B[K,N] + bias[N], OutT in {float,half}
// ---------------------------------------------------------------------------
__device__ __forceinline__ void store_out(float* p, float v) { *p = v; }
__device__ __forceinline__ void store_out(__half* p, float v) {
    *p = __float2half_rn(v);
}

template <typename OutT>
__global__ __launch_bounds__(128) void gemm_kernel(
    const float* __restrict__ A, const float* __restrict__ Bm,
    const float* __restrict__ bias, OutT* __restrict__ C,
    int M, int K, int N)
{
    __shared__ __align__(16) float As[16][68];
    __shared__ __align__(16) float Bs[16][64];
    const int m0 = blockIdx.x * 64;
    const int n0 = blockIdx.y * 64;
    const int tid = threadIdx.x;
    const int tx = tid & 15, ty = tid >> 4;

    float acc[8][4] = {};

    for (int k0 = 0; k0 < K; k0 += 16) {
#pragma unroll
        for (int i = 0; i < 8; i++) {
            const int e = i * 128 + tid;
            const int m = e >> 4, kk = e & 15;
            As[kk][m] = A[(size_t)(m0 + m) * K + k0 + kk];
        }
#pragma unroll
        for (int i = 0; i < 8; i++) {
            const int e = i * 128 + tid;
            const int kk = e >> 6, nn = e & 63;
            Bs[kk][nn] = Bm[(size_t)(k0 + kk) * N + n0 + nn];
        }
        __syncthreads();
#pragma unroll
        for (int kk = 0; kk < 16; kk++) {
            float4 b4  = *reinterpret_cast<const float4*>(&Bs[kk][tx * 4]);
            float4 alo = *reinterpret_cast<const float4*>(&As[kk][ty * 8]);
            float4 ahi = *reinterpret_cast<const float4*>(&As[kk][ty * 8 + 4]);
            const float a[8] = {alo.x, alo.y, alo.z, alo.w, ahi.x, ahi.y, ahi.z, ahi.w};
            const float bb[4] = {b4.x, b4.y, b4.z, b4.w};
#pragma unroll
            for (int q = 0; q < 8; q++)
#pragma unroll
                for (int j = 0; j < 4; j++)
                    acc[q][j] += a[q] * bb[j];
        }
        __syncthreads();
    }
#pragma unroll
    for (int q = 0; q < 8; q++) {
        const int m = m0 + ty * 8 + q;
#pragma unroll
        for (int j = 0; j < 4; j++) {
            const int n = n0 + tx * 4 + j;
            store_out(&C[(size_t)m * N + n], acc[q][j] + bias[n]);
        }
    }
}

// whatever_norm over last dim (256), in-place. grid = rows, block = 256.
__global__ __launch_bounds__(256) void norm_kernel(float* __restrict__ x)
{
    __shared__ float rs[256], rq[256];
    const int row = blockIdx.x, tid = threadIdx.x;
    const float v = x[(size_t)row * UU + tid];
    rs[tid] = v;
    rq[tid] = v * v;
    __syncthreads();
    for (int o = 128; o > 0; o >>= 1) {
        if (tid < o) { rs[tid] += rs[tid + o]; rq[tid] += rq[tid + o]; }
        __syncthreads();
    }
    const float mean = rs[0] * (1.0f / 256.0f);
    const float var = rq[0] * (1.0f / 256.0f) - mean * mean;
    const float sc = rsqrtf(var + 1e-4f);
    x[(size_t)row * UU + tid] = (v - mean) * sc;
}

// Row softmax over NC=64. block = 256 (8 warps -> 8 rows), grid = rows/8.
__global__ __launch_bounds__(256) void softmax_kernel(
    const float* __restrict__ in, float* __restrict__ outp)
{
    const int warp = threadIdx.x >> 5, lane = threadIdx.x & 31;
    const int row = blockIdx.x * 8 + warp;
    const float* p = in + (size_t)row * NC;
    float a = p[lane], b = p[lane + 32];
    float m = fmaxf(a, b);
#pragma unroll
    for (int o = 16; o; o >>= 1) m = fmaxf(m, __shfl_xor_sync(0xffffffffu, m, o));
    const float ea = expf(a - m), eb = expf(b - m);
    float s = ea + eb;
#pragma unroll
    for (int o = 16; o; o >>= 1) s += __shfl_xor_sync(0xffffffffu, s, o);
    const float inv = 1.0f / s;
    outp[(size_t)row * NC + lane] = ea * inv;
    outp[(size_t)row * NC + lane + 32] = eb * inv;
}

// ---------------------------------------------------------------------------
extern "C" void kernel_launch(void* const* d_in, const int* in_sizes, int n_in,
                              void* d_out, int out_size)
{
    const float* trans  = (const float*)d_in[0];
    const float* speech = (const float*)d_in[1];
    const float* embW   = (const float*)d_in[2];
    const float* embb   = (const float*)d_in[3];
    const float* Ua1W = (const float*)d_in[4];
    const float* Ua1b = (const float*)d_in[5];
    const float* Wa1W = (const float*)d_in[6];
    const float* Wa1b = (const float*)d_in[7];
    const float* va1W = (const float*)d_in[8];
    const float* va1b = (const float*)d_in[9];
    const float* K1   = (const float*)d_in[10];
    const float* R1   = (const float*)d_in[11];
    const float* b1   = (const float*)d_in[12];
    const float* Ua2W = (const float*)d_in[13];
    const float* Ua2b = (const float*)d_in[14];
    const float* Wa2W = (const float*)d_in[15];
    const float* Wa2b = (const float*)d_in[16];
    const float* va2W = (const float*)d_in[17];
    const float* va2b = (const float*)d_in[18];
    const float* K2   = (const float*)d_in[19];
    const float* R2   = (const float*)d_in[20];
    const float* b2   = (const float*)d_in[21];
    const float* m1W  = (const float*)d_in[22];
    const float* m1b  = (const float*)d_in[23];
    const float* m2W  = (const float*)d_in[24];
    const float* m2b  = (const float*)d_in[25];
    const float* dW   = (const float*)d_in[26];
    const float* db   = (const float*)d_in[27];

    float *secrets, *o2, *m1o, *m2o, *lg;
    __half *enc1h, *enc2h, *speechh;
    cudaGetSymbolAddress((void**)&secrets, d_secrets);
    cudaGetSymbolAddress((void**)&enc1h, d_enc1h);
    cudaGetSymbolAddress((void**)&enc2h, d_enc2h);
    cudaGetSymbolAddress((void**)&speechh, d_speechh);
    cudaGetSymbolAddress((void**)&o2, d_o2);
    cudaGetSymbolAddress((void**)&m1o, d_m1o);
    cudaGetSymbolAddress((void**)&m2o, d_m2o);
    cudaGetSymbolAddress((void**)&lg, d_lg);

    const int ROWS = BB * TT;      // 32768
    const int EROWS = BB * TE;     // 65536

    // One-time projections (enc written directly as fp16) + speech conversion
    gemm_kernel<<<dim3(ROWS / 64, UU / 64), 128>>>(trans, embW, embb, secrets, ROWS, NC, UU);
    gemm_kernel<<<dim3(EROWS / 64, UU / 64), 128>>>(speech, Ua1W, Ua1b, enc1h, EROWS, EE, UU);
    gemm_kernel<<<dim3(EROWS / 64, UU / 64), 128>>>(speech, Ua2W, Ua2b, enc2h, EROWS, EE, UU);
    {
        const int n8 = BB * TE * EE / 8;
        f2h_kernel<<<(n8 + 255) / 256, 256>>>(speech, speechh, n8);
    }

    // Both recurrent layers, pipelined, in ONE persistent kernel
    cudaFuncSetAttribute(decoder_persistent,
                         cudaFuncAttributeMaxDynamicSharedMemorySize, DSM_BYTES);
    decoder_persistent<<<128, 512, DSM_BYTES>>>(
        Wa1W, Wa1b, va1W, va1b, K1, R1, b1,
        Wa2W, Wa2b, va2W, va2b, K2, R2, b2);

    // MLP head
    norm_kernel<<<ROWS, 256>>>(o2);
    gemm_kernel<<<dim3(ROWS / 64, UU / 64), 128>>>(o2, m1W, m1b, m1o, ROWS, UU, UU);
    norm_kernel<<<ROWS, 256>>>(m1o);
    gemm_kernel<<<dim3(ROWS / 64, UU / 64), 128>>>(m1o, m2W, m2b, m2o, ROWS, UU, UU);
    norm_kernel<<<ROWS, 256>>>(m2o);
    gemm_kernel<<<dim3(ROWS / 64, NC / 64), 128>>>(m2o, dW, db, lg, ROWS, UU, NC);
    softmax_kernel<<<ROWS / 8, 256>>>(lg, (float*)d_out);

    (void)in_sizes; (void)n_in; (void)out_size;
}

// round 16
// speedup vs baseline: 1.1344x; 1.1344x over previous
#include <cuda_runtime.h>
#include <cuda_fp16.h>
#include <math.h>

#define BB 64      // batch
#define TT 512     // decode steps
#define TE 1024    // encoder steps
#define EE 512     // encoder dim
#define UU 256     // units
#define NC 64      // classes
#define GG 1024    // 4*U gates
#define VV 1024    // U (x) + E (ctx) + U (h)

#define STAGE_BYTES 49152          // enc 16 KB + speech 32 KB
#define RED_OFF     98304          // red area after the two stages
#define DSM_BYTES   102400         // 96 KB stages + 4 KB red

// ---------------- scratch (static device globals; no allocation) -------------
__device__ float d_secrets[BB * TT * UU];
__device__ __half d_enc1h[BB * TE * UU];   // fp16 enc, layer1
__device__ __half d_enc2h[BB * TE * UU];   // fp16 enc, layer2
__device__ __half d_speechh[BB * TE * EE]; // fp16 speech
__device__ float d_o1[BB * TT * UU];
__device__ float d_o2[BB * TT * UU];
__device__ float d_m1o[BB * TT * UU];
__device__ float d_m2o[BB * TT * UU];
__device__ float d_lg[BB * TT * NC];
__device__ float d_vT[2 * VV * BB];      // [layer][row 0..1023][batch]  (transposed v)
__device__ float d_Z[2 * BB * GG];       // [layer][batch][gate]
__device__ unsigned d_bar[128];          // grid-barrier flags (monotone)

__device__ __forceinline__ float tanh_fast(float x) {
    float y;
    asm("tanh.approx.f32 %0, %1;" : "=f"(y) : "f"(x));
    return y;
}

// -------- TMA 1D bulk copy global->shared, mbarrier completion --------------
__device__ __forceinline__ void bulk_g2s(unsigned sdst, const void* gsrc,
                                         unsigned bytes, unsigned mbar) {
    asm volatile(
        "cp.async.bulk.shared::cluster.global.mbarrier::complete_tx::bytes "
        "[%0], [%1], %2, [%3];"
        :: "r"(sdst), "l"(gsrc), "r"(bytes), "r"(mbar) : "memory");
}

__device__ __forceinline__ void mbar_expect_tx(unsigned mbar, unsigned tx) {
    asm volatile("mbarrier.arrive.expect_tx.shared.b64 _, [%0], %1;"
                 :: "r"(mbar), "r"(tx) : "memory");
}

__device__ __forceinline__ void mbar_wait(unsigned mbar, unsigned parity) {
    unsigned done;
    asm volatile(
        "{\n\t.reg .pred p;\n\t"
        "mbarrier.try_wait.parity.acquire.cta.shared::cta.b64 p, [%1], %2;\n\t"
        "selp.b32 %0, 1, 0, p;\n\t}"
        : "=r"(done) : "r"(mbar), "r"(parity) : "memory");
    if (!done) {
        asm volatile(
            "{\n\t.reg .pred P1;\n\t"
            "WL_%=:\n\t"
            "mbarrier.try_wait.parity.acquire.cta.shared::cta.b64 P1, [%0], %1, 0x989680;\n\t"
            "@P1 bra.uni WD_%=;\n\t"
            "bra.uni WL_%=;\n\t"
            "WD_%=:\n\t}"
            :: "r"(mbar), "r"(parity) : "memory");
    }
}

// -------- grid barrier: release/acquire flags, monotone phase ---------------
__device__ __forceinline__ void gbar(unsigned& ph) {
    __threadfence();
    __syncthreads();
    ph++;
    if (threadIdx.x == 0) {
        asm volatile("st.release.gpu.global.u32 [%0], %1;"
                     :: "l"(&d_bar[blockIdx.x]), "r"(ph) : "memory");
    }
    if (threadIdx.x < 128) {
        unsigned v;
        do {
            asm volatile("ld.acquire.gpu.global.u32 %0, [%1];"
                         : "=r"(v) : "l"(&d_bar[threadIdx.x]) : "memory");
        } while ((int)(v - ph) < 0);
    }
    __syncthreads();
    __threadfence();
}

// ---------------------------------------------------------------------------
// Persistent decoder: both attention-LSTM layers, pipelined (layer2 one step
// behind layer1). grid = 128 CTAs (L = bid/64, b = bid%64), block = 512.
// Fused attention streams te in 32-row blocks staged via TMA bulk copies
// (double buffer, distance-2 prefetch), online softmax + ctx per warp,
// exact 16-way merge.
// ---------------------------------------------------------------------------
__global__ __launch_bounds__(512, 1) void decoder_persistent(
    const float* __restrict__ Wa1W, const float* __restrict__ Wa1b,
    const float* __restrict__ va1W, const float* __restrict__ va1b,
    const float* __restrict__ K1, const float* __restrict__ R1, const float* __restrict__ b1,
    const float* __restrict__ Wa2W, const float* __restrict__ Wa2b,
    const float* __restrict__ va2W, const float* __restrict__ va2b,
    const float* __restrict__ K2, const float* __restrict__ R2, const float* __restrict__ b2)
{
    extern __shared__ __align__(16) char dsm[];

    const int bid = blockIdx.x;
    const int tid = threadIdx.x;
    const int L = bid >> 6;         // 0 = layer1, 1 = layer2
    const int b = bid & 63;
    const int lane = tid & 31, warp = tid >> 5;   // 16 warps

    const __half* ench = L ? d_enc2h : d_enc1h;
    const float* WaW = L ? Wa2W : Wa1W;
    const float* Wab = L ? Wa2b : Wa1b;
    const float* vaW = L ? va2W : va1W;
    const float* Kw  = L ? K2 : K1;
    const float* Rw  = L ? R2 : R1;
    const float* bz  = L ? b2 : b1;
    float* outbuf = L ? d_o2 : d_o1;
    float* vT = d_vT + L * (VV * BB);
    float* Zl = d_Z + L * (BB * GG);

    const char* encG = (const char*)(ench + (size_t)b * TE * UU);        // 512 B rows
    const char* spG  = (const char*)(d_speechh + (size_t)b * TE * EE);   // 1024 B rows
    const unsigned smemBase = (unsigned)__cvta_generic_to_shared(dsm);

    __shared__ float sh_h[UU];
    __shared__ float sh_s[UU];
    __shared__ float sm_m[16], sm_s[16];
    __shared__ __align__(8) unsigned long long sm_mbar[2];
    float* red = (float*)(dsm + RED_OFF);      // 1024 floats

    const unsigned mbar0 = (unsigned)__cvta_generic_to_shared(&sm_mbar[0]);
    const unsigned mbar1 = (unsigned)__cvta_generic_to_shared(&sm_mbar[1]);

    if (tid == 0) {
        asm volatile("mbarrier.init.shared.b64 [%0], 1;" :: "r"(mbar0) : "memory");
        asm volatile("mbarrier.init.shared.b64 [%0], 1;" :: "r"(mbar1) : "memory");
        asm volatile("fence.proxy.async.shared::cta;" ::: "memory");
    }
    __syncthreads();

    unsigned par0 = 0, par1 = 0;   // mbarrier phase parity (per thread, uniform)
    float c_reg = 0.0f;            // cell state (threads 0..255)
    unsigned ph = *((volatile unsigned*)&d_bar[bid]);

    for (int k = 0; k <= 513; k++) {
        const int t = k - L;                    // this layer's step
        const bool attnAct = (t >= 0) && (t < TT);
        const bool gateAct = (t >= 1) && (t <= TT);

        if (k) gbar(ph);   // B0: Z of previous iteration complete

        // ---- prologue: stage te-blocks 0 and 1 (hidden by phases A/1) ----
        if (attnAct && tid == 0) {
            mbar_expect_tx(mbar0, STAGE_BYTES);
            bulk_g2s(smemBase,          encG, 16384, mbar0);
            bulk_g2s(smemBase + 16384,  spG,  32768, mbar0);
            mbar_expect_tx(mbar1, STAGE_BYTES);
            bulk_g2s(smemBase + STAGE_BYTES,         encG + 16384, 16384, mbar1);
            bulk_g2s(smemBase + STAGE_BYTES + 16384, spG + 32768,  32768, mbar1);
        }

        // ---------------- phase A: gates -> h_{t-1} ------------------------
        if (tid < UU) {
            if (gateAct) {
                const float* Zb = Zl + b * GG;
                float zi = bz[tid]       + __ldcg(Zb + tid);
                float zf = bz[tid + 256] + __ldcg(Zb + tid + 256);
                float zg = bz[tid + 512] + __ldcg(Zb + tid + 512);
                float zo = bz[tid + 768] + __ldcg(Zb + tid + 768);
                float ig = 1.0f / (1.0f + expf(-zi));
                float fg = 1.0f / (1.0f + expf(-zf));
                float og = 1.0f / (1.0f + expf(-zo));
                c_reg = fg * c_reg + ig * tanhf(zg);
                float h = og * tanhf(c_reg);
                sh_h[tid] = h;
                __stcg(vT + (768 + tid) * BB + b, h);
                __stcg(outbuf + ((size_t)b * TT + (t - 1)) * UU + tid, h);
            } else if (attnAct) {   // t == 0 init
                c_reg = 0.0f;
                sh_h[tid] = 0.0f;
                __stcg(vT + (768 + tid) * BB + b, 0.0f);
            }
        }

        gbar(ph);          // B1: h / o1 rows visible grid-wide

        if (attnAct) {
            // ---- x_t (layer2: norm of layer1's h_t, written this iter) ----
            float xv = 0.0f;
            if (tid < UU) {
                xv = (L == 0) ? d_secrets[((size_t)b * TT + t) * UU + tid]
                              : __ldcg(d_o1 + ((size_t)b * TT + t) * UU + tid);
            }
            if (L == 1) {   // uniform per CTA -> syncthreads legal
                red[tid]       = (tid < UU) ? xv : 0.0f;
                red[512 + tid] = (tid < UU) ? xv * xv : 0.0f;
                __syncthreads();
                for (int o = 256; o > 0; o >>= 1) {
                    if (tid < o) {
                        red[tid] += red[tid + o];
                        red[512 + tid] += red[512 + tid + o];
                    }
                    __syncthreads();
                }
                const float mean = red[0] * (1.0f / 256.0f);
                const float var  = red[512] * (1.0f / 256.0f) - mean * mean;
                const float sc = rsqrtf(var + 1e-4f);
                xv = (xv - mean) * sc;
                __syncthreads();
            }
            if (tid < UU) __stcg(vT + tid * BB + b, xv);

            // ---- phase 1: s = h @ Wa + Wa_b -------------------------------
            {
                const int uu = tid & 255, half = tid >> 8;
                float acc = 0.0f;
                const float* wp = WaW + (size_t)(half * 128) * UU + uu;
#pragma unroll 8
                for (int kk = 0; kk < 128; kk++)
                    acc += sh_h[half * 128 + kk] * wp[(size_t)kk * UU];
                red[tid] = acc;
                __syncthreads();
                if (tid < UU) sh_s[tid] = red[tid] + red[tid + 256] + Wab[tid];
                __syncthreads();
            }

            // ---- FUSED phases 2-4: TMA-staged online softmax + ctx --------
            {
                float va_r[8], s_r[8];
#pragma unroll
                for (int j = 0; j < 8; j++) {
                    va_r[j] = vaW[lane * 8 + j];
                    s_r[j]  = sh_s[lane * 8 + j];
                }

                float m = -1e30f, s = 0.0f;
                float acc[16];
#pragma unroll
                for (int i = 0; i < 16; i++) acc[i] = 0.0f;

                const int r0 = warp * 2, r1 = r0 + 1;

#pragma unroll 1
                for (int blk = 0; blk < 32; blk++) {
                    const int cur = blk & 1;
                    // wait for this block's fill
                    if (cur == 0) { mbar_wait(mbar0, par0); par0 ^= 1; }
                    else          { mbar_wait(mbar1, par1); par1 ^= 1; }

                    const uint4* eP = (const uint4*)(dsm + cur * STAGE_BYTES);
                    const uint4* sP = (const uint4*)(dsm + cur * STAGE_BYTES + 16384);
                    uint4 e0  = eP[r0 * 32 + lane];
                    uint4 e1  = eP[r1 * 32 + lane];
                    uint4 sA0 = sP[r0 * 64 + lane];
                    uint4 sB0 = sP[r0 * 64 + 32 + lane];
                    uint4 sA1 = sP[r1 * 64 + lane];
                    uint4 sB1 = sP[r1 * 64 + 32 + lane];

                    float l0 = 0.f, l1 = 0.f;
                    {
                        const __half2* h0 = reinterpret_cast<const __half2*>(&e0);
                        const __half2* h1 = reinterpret_cast<const __half2*>(&e1);
#pragma unroll
                        for (int pp = 0; pp < 4; pp++) {
                            float2 f0 = __half22float2(h0[pp]);
                            float2 f1 = __half22float2(h1[pp]);
                            l0 += va_r[2 * pp]     * tanh_fast(s_r[2 * pp]     + f0.x);
                            l1 += va_r[2 * pp]     * tanh_fast(s_r[2 * pp]     + f1.x);
                            l0 += va_r[2 * pp + 1] * tanh_fast(s_r[2 * pp + 1] + f0.y);
                            l1 += va_r[2 * pp + 1] * tanh_fast(s_r[2 * pp + 1] + f1.y);
                        }
                    }
#pragma unroll
                    for (int o = 16; o; o >>= 1) {
                        l0 += __shfl_xor_sync(0xffffffffu, l0, o);
                        l1 += __shfl_xor_sync(0xffffffffu, l1, o);
                    }

                    // row r0 (warp-uniform branch)
                    if (l0 > m) {
                        const float corr = __expf(m - l0);
                        m = l0;
                        s *= corr;
#pragma unroll
                        for (int i = 0; i < 16; i++) acc[i] *= corr;
                    }
                    {
                        const float w = __expf(l0 - m);
                        s += w;
                        const __half2* hA = reinterpret_cast<const __half2*>(&sA0);
                        const __half2* hB = reinterpret_cast<const __half2*>(&sB0);
#pragma unroll
                        for (int pp = 0; pp < 4; pp++) {
                            float2 fa = __half22float2(hA[pp]);
                            float2 fb = __half22float2(hB[pp]);
                            acc[2 * pp]         += w * fa.x;
                            acc[2 * pp + 1]     += w * fa.y;
                            acc[8 + 2 * pp]     += w * fb.x;
                            acc[8 + 2 * pp + 1] += w * fb.y;
                        }
                    }
                    // row r1
                    if (l1 > m) {
                        const float corr = __expf(m - l1);
                        m = l1;
                        s *= corr;
#pragma unroll
                        for (int i = 0; i < 16; i++) acc[i] *= corr;
                    }
                    {
                        const float w = __expf(l1 - m);
                        s += w;
                        const __half2* hA = reinterpret_cast<const __half2*>(&sA1);
                        const __half2* hB = reinterpret_cast<const __half2*>(&sB1);
#pragma unroll
                        for (int pp = 0; pp < 4; pp++) {
                            float2 fa = __half22float2(hA[pp]);
                            float2 fb = __half22float2(hB[pp]);
                            acc[2 * pp]         += w * fa.x;
                            acc[2 * pp + 1]     += w * fa.y;
                            acc[8 + 2 * pp]     += w * fb.x;
                            acc[8 + 2 * pp + 1] += w * fb.y;
                        }
                    }

                    __syncthreads();   // everyone done reading stage cur
                    // refill buffer cur with block blk+2 (distance-2)
                    if (tid == 0 && blk + 2 < 32) {
                        const unsigned st = smemBase + cur * STAGE_BYTES;
                        const unsigned mb = cur ? mbar1 : mbar0;
                        mbar_expect_tx(mb, STAGE_BYTES);
                        bulk_g2s(st,         encG + (size_t)(blk + 2) * 16384, 16384, mb);
                        bulk_g2s(st + 16384, spG  + (size_t)(blk + 2) * 32768, 32768, mb);
                    }
                }

                // ---- exact 16-way flash merge across warps ----------------
                if (lane == 0) { sm_m[warp] = m; sm_s[warp] = s; }
                __syncthreads();
                float M = sm_m[0];
#pragma unroll
                for (int w2 = 1; w2 < 16; w2++) M = fmaxf(M, sm_m[w2]);
                float S = 0.0f;
#pragma unroll
                for (int w2 = 0; w2 < 16; w2++)
                    S += sm_s[w2] * __expf(sm_m[w2] - M);
                const float fw = __expf(m - M);
                const float invS = 1.0f / S;
                float* buf = (float*)dsm;      // [16][512]
                {
                    float4 v0 = make_float4(acc[0] * fw, acc[1] * fw,
                                            acc[2] * fw, acc[3] * fw);
                    float4 v1 = make_float4(acc[4] * fw, acc[5] * fw,
                                            acc[6] * fw, acc[7] * fw);
                    float4 v2 = make_float4(acc[8] * fw, acc[9] * fw,
                                            acc[10] * fw, acc[11] * fw);
                    float4 v3 = make_float4(acc[12] * fw, acc[13] * fw,
                                            acc[14] * fw, acc[15] * fw);
                    float4* bp = reinterpret_cast<float4*>(buf + warp * 512);
                    bp[lane * 2]           = v0;
                    bp[lane * 2 + 1]       = v1;
                    bp[64 + lane * 2]      = v2;
                    bp[64 + lane * 2 + 1]  = v3;
                }
                __syncthreads();
                float ctx = 0.0f;
#pragma unroll
                for (int w2 = 0; w2 < 16; w2++)
                    ctx += buf[w2 * 512 + tid];
                __stcg(vT + (256 + tid) * BB + b, ctx * invS);
            }
        }

        gbar(ph);          // B2: v (all batches, this layer) visible

        // ---------------- phase D: Z[:, 16 cols] = v @ [K;R] ----------------
        if (attnAct) {
            float (*vsh)[68] = reinterpret_cast<float(*)[68]>((float*)dsm);
            float (*wsh)[20] = reinterpret_cast<float(*)[20]>((float*)dsm + 64 * 68);
            const int c0 = b * 16;
            const int rg = tid & 7, cg = (tid >> 3) & 3, bg = tid >> 5;
            float acc[4][4] = {};

            for (int tile = 0; tile < 16; tile++) {
                const int rbase = tile * 64;
#pragma unroll
                for (int i = 0; i < 2; i++) {
                    const int e4i = i * 512 + tid;
                    const int r = e4i >> 4, b4 = e4i & 15;
                    float4 vv = __ldcg(
                        reinterpret_cast<const float4*>(vT + (size_t)(rbase + r) * BB) + b4);
                    *reinterpret_cast<float4*>(&vsh[r][b4 * 4]) = vv;
                }
                if (tid < 256) {
                    const int r = tid >> 2, c4 = tid & 3;
                    const int gr = rbase + r;
                    const float* Wrow = (gr < 768) ? (Kw + (size_t)gr * GG)
                                                   : (Rw + (size_t)(gr - 768) * GG);
                    *reinterpret_cast<float4*>(&wsh[r][c4 * 4]) =
                        *reinterpret_cast<const float4*>(Wrow + c0 + c4 * 4);
                }
                __syncthreads();
#pragma unroll
                for (int rr = 0; rr < 8; rr++) {
                    const int r = rr * 8 + rg;
                    float4 vv = *reinterpret_cast<const float4*>(&vsh[r][bg * 4]);
                    float4 ww = *reinterpret_cast<const float4*>(&wsh[r][cg * 4]);
                    const float vvv[4] = {vv.x, vv.y, vv.z, vv.w};
                    const float www[4] = {ww.x, ww.y, ww.z, ww.w};
#pragma unroll
                    for (int i = 0; i < 4; i++)
#pragma unroll
                        for (int j = 0; j < 4; j++)
                            acc[i][j] += vvv[i] * www[j];
                }
                __syncthreads();
            }
            // reduce over rg (lane bits 0..2)
#pragma unroll
            for (int i = 0; i < 4; i++)
#pragma unroll
                for (int j = 0; j < 4; j++) {
                    float a = acc[i][j];
                    a += __shfl_xor_sync(0xffffffffu, a, 1);
                    a += __shfl_xor_sync(0xffffffffu, a, 2);
                    a += __shfl_xor_sync(0xffffffffu, a, 4);
                    acc[i][j] = a;
                }
            if (rg == 0) {
#pragma unroll
                for (int i = 0; i < 4; i++)
#pragma unroll
                    for (int j = 0; j < 4; j++)
                        __stcg(Zl + (size_t)(bg * 4 + i) * GG + c0 + cg * 4 + j, acc[i][j]);
            }
        }
    }
}

// ---------------------------------------------------------------------------
// fp32 -> fp16 bulk convert, 8 elems/thread.
// ---------------------------------------------------------------------------
__global__ __launch_bounds__(256) void f2h_kernel(
    const float* __restrict__ in, __half* __restrict__ out, int n8)
{
    const int i = blockIdx.x * blockDim.x + threadIdx.x;
    if (i >= n8) return;
    const float4* p = reinterpret_cast<const float4*>(in) + 2 * i;
    float4 a = p[0], c = p[1];
    __half2 h0 = __floats2half2_rn(a.x, a.y);
    __half2 h1 = __floats2half2_rn(a.z, a.w);
    __half2 h2 = __floats2half2_rn(c.x, c.y);
    __half2 h3 = __floats2half2_rn(c.z, c.w);
    uint4 q;
    q.x = *reinterpret_cast<unsigned*>(&h0);
    q.y = *reinterpret_cast<unsigned*>(&h1);
    q.z = *reinterpret_cast<unsigned*>(&h2);
    q.w = *reinterpret_cast<unsigned*>(&h3);
    reinterpret_cast<uint4*>(out)[i] = q;
}

// ---------------------------------------------------------------------------
// Generic tiled SGEMM: C[M,N] = A[M,K] @ B[K,N] + bias[N], OutT in {float,half}
// ---------------------------------------------------------------------------
__device__ __forceinline__ void store_out(float* p, float v) { *p = v; }
__device__ __forceinline__ void store_out(__half* p, float v) {
    *p = __float2half_rn(v);
}

template <typename OutT>
__global__ __launch_bounds__(128) void gemm_kernel(
    const float* __restrict__ A, const float* __restrict__ Bm,
    const float* __restrict__ bias, OutT* __restrict__ C,
    int M, int K, int N)
{
    __shared__ __align__(16) float As[16][68];
    __shared__ __align__(16) float Bs[16][64];
    const int m0 = blockIdx.x * 64;
    const int n0 = blockIdx.y * 64;
    const int tid = threadIdx.x;
    const int tx = tid & 15, ty = tid >> 4;

    float acc[8][4] = {};

    for (int k0 = 0; k0 < K; k0 += 16) {
#pragma unroll
        for (int i = 0; i < 8; i++) {
            const int e = i * 128 + tid;
            const int m = e >> 4, kk = e & 15;
            As[kk][m] = A[(size_t)(m0 + m) * K + k0 + kk];
        }
#pragma unroll
        for (int i = 0; i < 8; i++) {
            const int e = i * 128 + tid;
            const int kk = e >> 6, nn = e & 63;
            Bs[kk][nn] = Bm[(size_t)(k0 + kk) * N + n0 + nn];
        }
        __syncthreads();
#pragma unroll
        for (int kk = 0; kk < 16; kk++) {
            float4 b4  = *reinterpret_cast<const float4*>(&Bs[kk][tx * 4]);
            float4 alo = *reinterpret_cast<const float4*>(&As[kk][ty * 8]);
            float4 ahi = *reinterpret_cast<const float4*>(&As[kk][ty * 8 + 4]);
            const float a[8] = {alo.x, alo.y, alo.z, alo.w, ahi.x, ahi.y, ahi.z, ahi.w};
            const float bb[4] = {b4.x, b4.y, b4.z, b4.w};
#pragma unroll
            for (int q = 0; q < 8; q++)
#pragma unroll
                for (int j = 0; j < 4; j++)
                    acc[q][j] += a[q] * bb[j];
        }
        __syncthreads();
    }
#pragma unroll
    for (int q = 0; q < 8; q++) {
        const int m = m0 + ty * 8 + q;
#pragma unroll
        for (int j = 0; j < 4; j++) {
            const int n = n0 + tx * 4 + j;
            store_out(&C[(size_t)m * N + n], acc[q][j] + bias[n]);
        }
    }
}

// whatever_norm over last dim (256), in-place. grid = rows, block = 256.
__global__ __launch_bounds__(256) void norm_kernel(float* __restrict__ x)
{
    __shared__ float rs[256], rq[256];
    const int row = blockIdx.x, tid = threadIdx.x;
    const float v = x[(size_t)row * UU + tid];
    rs[tid] = v;
    rq[tid] = v * v;
    __syncthreads();
    for (int o = 128; o > 0; o >>= 1) {
        if (tid < o) { rs[tid] += rs[tid + o]; rq[tid] += rq[tid + o]; }
        __syncthreads();
    }
    const float mean = rs[0] * (1.0f / 256.0f);
    const float var = rq[0] * (1.0f / 256.0f) - mean * mean;
    const float sc = rsqrtf(var + 1e-4f);
    x[(size_t)row * UU + tid] = (v - mean) * sc;
}

// Row softmax over NC=64. block = 256 (8 warps -> 8 rows), grid = rows/8.
__global__ __launch_bounds__(256) void softmax_kernel(
    const float* __restrict__ in, float* __restrict__ outp)
{
    const int warp = threadIdx.x >> 5, lane = threadIdx.x & 31;
    const int row = blockIdx.x * 8 + warp;
    const float* p = in + (size_t)row * NC;
    float a = p[lane], b = p[lane + 32];
    float m = fmaxf(a, b);
#pragma unroll
    for (int o = 16; o; o >>= 1) m = fmaxf(m, __shfl_xor_sync(0xffffffffu, m, o));
    const float ea = expf(a - m), eb = expf(b - m);
    float s = ea + eb;
#pragma unroll
    for (int o = 16; o; o >>= 1) s += __shfl_xor_sync(0xffffffffu, s, o);
    const float inv = 1.0f / s;
    outp[(size_t)row * NC + lane] = ea * inv;
    outp[(size_t)row * NC + lane + 32] = eb * inv;
}

// ---------------------------------------------------------------------------
extern "C" void kernel_launch(void* const* d_in, const int* in_sizes, int n_in,
                              void* d_out, int out_size)
{
    const float* trans  = (const float*)d_in[0];
    const float* speech = (const float*)d_in[1];
    const float* embW   = (const float*)d_in[2];
    const float* embb   = (const float*)d_in[3];
    const float* Ua1W = (const float*)d_in[4];
    const float* Ua1b = (const float*)d_in[5];
    const float* Wa1W = (const float*)d_in[6];
    const float* Wa1b = (const float*)d_in[7];
    const float* va1W = (const float*)d_in[8];
    const float* va1b = (const float*)d_in[9];
    const float* K1   = (const float*)d_in[10];
    const float* R1   = (const float*)d_in[11];
    const float* b1   = (const float*)d_in[12];
    const float* Ua2W = (const float*)d_in[13];
    const float* Ua2b = (const float*)d_in[14];
    const float* Wa2W = (const float*)d_in[15];
    const float* Wa2b = (const float*)d_in[16];
    const float* va2W = (const float*)d_in[17];
    const float* va2b = (const float*)d_in[18];
    const float* K2   = (const float*)d_in[19];
    const float* R2   = (const float*)d_in[20];
    const float* b2   = (const float*)d_in[21];
    const float* m1W  = (const float*)d_in[22];
    const float* m1b  = (const float*)d_in[23];
    const float* m2W  = (const float*)d_in[24];
    const float* m2b  = (const float*)d_in[25];
    const float* dW   = (const float*)d_in[26];
    const float* db   = (const float*)d_in[27];

    float *secrets, *o2, *m1o, *m2o, *lg;
    __half *enc1h, *enc2h, *speechh;
    cudaGetSymbolAddress((void**)&secrets, d_secrets);
    cudaGetSymbolAddress((void**)&enc1h, d_enc1h);
    cudaGetSymbolAddress((void**)&enc2h, d_enc2h);
    cudaGetSymbolAddress((void**)&speechh, d_speechh);
    cudaGetSymbolAddress((void**)&o2, d_o2);
    cudaGetSymbolAddress((void**)&m1o, d_m1o);
    cudaGetSymbolAddress((void**)&m2o, d_m2o);
    cudaGetSymbolAddress((void**)&lg, d_lg);

    const int ROWS = BB * TT;      // 32768
    const int EROWS = BB * TE;     // 65536

    // One-time projections (enc written directly as fp16) + speech conversion
    gemm_kernel<<<dim3(ROWS / 64, UU / 64), 128>>>(trans, embW, embb, secrets, ROWS, NC, UU);
    gemm_kernel<<<dim3(EROWS / 64, UU / 64), 128>>>(speech, Ua1W, Ua1b, enc1h, EROWS, EE, UU);
    gemm_kernel<<<dim3(EROWS / 64, UU / 64), 128>>>(speech, Ua2W, Ua2b, enc2h, EROWS, EE, UU);
    {
        const int n8 = BB * TE * EE / 8;
        f2h_kernel<<<(n8 + 255) / 256, 256>>>(speech, speechh, n8);
    }

    // Both recurrent layers, pipelined, in ONE persistent kernel
    cudaFuncSetAttribute(decoder_persistent,
                         cudaFuncAttributeMaxDynamicSharedMemorySize, DSM_BYTES);
    decoder_persistent<<<128, 512, DSM_BYTES>>>(
        Wa1W, Wa1b, va1W, va1b, K1, R1, b1,
        Wa2W, Wa2b, va2W, va2b, K2, R2, b2);

    // MLP head
    norm_kernel<<<ROWS, 256>>>(o2);
    gemm_kernel<<<dim3(ROWS / 64, UU / 64), 128>>>(o2, m1W, m1b, m1o, ROWS, UU, UU);
    norm_kernel<<<ROWS, 256>>>(m1o);
    gemm_kernel<<<dim3(ROWS / 64, UU / 64), 128>>>(m1o, m2W, m2b, m2o, ROWS, UU, UU);
    norm_kernel<<<ROWS, 256>>>(m2o);
    gemm_kernel<<<dim3(ROWS / 64, NC / 64), 128>>>(m2o, dW, db, lg, ROWS, UU, NC);
    softmax_kernel<<<ROWS / 8, 256>>>(lg, (float*)d_out);

    (void)in_sizes; (void)n_in; (void)out_size;
}

// round 17
// speedup vs baseline: 1.2161x; 1.0721x over previous
#include <cuda_runtime.h>
#include <cuda_fp16.h>
#include <math.h>

#define BB 64      // batch
#define TT 512     // decode steps
#define TE 1024    // encoder steps
#define EE 512     // encoder dim
#define UU 256     // units
#define NC 64      // classes
#define GG 1024    // 4*U gates
#define VV 1024    // U (x) + E (ctx) + U (h)

#define STAGE_BYTES 49152          // enc 16 KB + speech 32 KB
#define RED_OFF     98304          // red area after the two stages
#define DSM_BYTES   102400         // 96 KB stages + 4 KB red

// ---------------- scratch (static device globals; no allocation) -------------
__device__ float d_secrets[BB * TT * UU];
__device__ __half d_enc1h[BB * TE * UU];   // fp16 enc, layer1
__device__ __half d_enc2h[BB * TE * UU];   // fp16 enc, layer2
__device__ __half d_speechh[BB * TE * EE]; // fp16 speech
__device__ float d_o1[BB * TT * UU];
__device__ float d_o2[BB * TT * UU];
__device__ float d_m1o[BB * TT * UU];
__device__ float d_m2o[BB * TT * UU];
__device__ float d_lg[BB * TT * NC];
__device__ float d_vT[2 * VV * BB];      // [layer][row 0..1023][batch]  (transposed v)
__device__ float d_Z[2 * BB * GG];       // [layer][batch][gate]
__device__ unsigned d_bar[128];          // grid-barrier flags (monotone)

__device__ __forceinline__ __half2 tanh2(__half2 x) {
    unsigned xi = *reinterpret_cast<unsigned*>(&x), y;
    asm("tanh.approx.f16x2 %0, %1;" : "=r"(y) : "r"(xi));
    return *reinterpret_cast<__half2*>(&y);
}

// -------- TMA 1D bulk copy global->shared, mbarrier completion --------------
__device__ __forceinline__ void bulk_g2s(unsigned sdst, const void* gsrc,
                                         unsigned bytes, unsigned mbar) {
    asm volatile(
        "cp.async.bulk.shared::cluster.global.mbarrier::complete_tx::bytes "
        "[%0], [%1], %2, [%3];"
        :: "r"(sdst), "l"(gsrc), "r"(bytes), "r"(mbar) : "memory");
}

__device__ __forceinline__ void mbar_expect_tx(unsigned mbar, unsigned tx) {
    asm volatile("mbarrier.arrive.expect_tx.shared.b64 _, [%0], %1;"
                 :: "r"(mbar), "r"(tx) : "memory");
}

__device__ __forceinline__ void mbar_wait(unsigned mbar, unsigned parity) {
    unsigned done;
    asm volatile(
        "{\n\t.reg .pred p;\n\t"
        "mbarrier.try_wait.parity.acquire.cta.shared::cta.b64 p, [%1], %2;\n\t"
        "selp.b32 %0, 1, 0, p;\n\t}"
        : "=r"(done) : "r"(mbar), "r"(parity) : "memory");
    if (!done) {
        asm volatile(
            "{\n\t.reg .pred P1;\n\t"
            "WL_%=:\n\t"
            "mbarrier.try_wait.parity.acquire.cta.shared::cta.b64 P1, [%0], %1, 0x989680;\n\t"
            "@P1 bra.uni WD_%=;\n\t"
            "bra.uni WL_%=;\n\t"
            "WD_%=:\n\t}"
            :: "r"(mbar), "r"(parity) : "memory");
    }
}

// -------- grid barrier: release/acquire flags, monotone phase ---------------
__device__ __forceinline__ void gbar(unsigned& ph) {
    __threadfence();
    __syncthreads();
    ph++;
    if (threadIdx.x == 0) {
        asm volatile("st.release.gpu.global.u32 [%0], %1;"
                     :: "l"(&d_bar[blockIdx.x]), "r"(ph) : "memory");
    }
    if (threadIdx.x < 128) {
        unsigned v;
        do {
            asm volatile("ld.acquire.gpu.global.u32 %0, [%1];"
                         : "=r"(v) : "l"(&d_bar[threadIdx.x]) : "memory");
        } while ((int)(v - ph) < 0);
    }
    __syncthreads();
    __threadfence();
}

// ---------------------------------------------------------------------------
// Persistent decoder: both attention-LSTM layers, pipelined (layer2 TWO steps
// behind layer1 -> only 2 grid barriers per iteration).
// grid = 128 CTAs (L = bid/64, b = bid%64), block = 512.
// Fused attention streams te in 32-row blocks staged via TMA bulk copies
// (double buffer, distance-2 prefetch), online softmax + ctx per warp
// (tanh.approx.f16x2 logits, fp32 accumulate), exact 16-way merge.
// ---------------------------------------------------------------------------
__global__ __launch_bounds__(512, 1) void decoder_persistent(
    const float* __restrict__ Wa1W, const float* __restrict__ Wa1b,
    const float* __restrict__ va1W, const float* __restrict__ va1b,
    const float* __restrict__ K1, const float* __restrict__ R1, const float* __restrict__ b1,
    const float* __restrict__ Wa2W, const float* __restrict__ Wa2b,
    const float* __restrict__ va2W, const float* __restrict__ va2b,
    const float* __restrict__ K2, const float* __restrict__ R2, const float* __restrict__ b2)
{
    extern __shared__ __align__(16) char dsm[];

    const int bid = blockIdx.x;
    const int tid = threadIdx.x;
    const int L = bid >> 6;         // 0 = layer1, 1 = layer2
    const int b = bid & 63;
    const int lane = tid & 31, warp = tid >> 5;   // 16 warps

    const __half* ench = L ? d_enc2h : d_enc1h;
    const float* WaW = L ? Wa2W : Wa1W;
    const float* Wab = L ? Wa2b : Wa1b;
    const float* vaW = L ? va2W : va1W;
    const float* Kw  = L ? K2 : K1;
    const float* Rw  = L ? R2 : R1;
    const float* bz  = L ? b2 : b1;
    float* outbuf = L ? d_o2 : d_o1;
    float* vT = d_vT + L * (VV * BB);
    float* Zl = d_Z + L * (BB * GG);

    const char* encG = (const char*)(ench + (size_t)b * TE * UU);        // 512 B rows
    const char* spG  = (const char*)(d_speechh + (size_t)b * TE * EE);   // 1024 B rows
    const unsigned smemBase = (unsigned)__cvta_generic_to_shared(dsm);

    __shared__ float sh_h[UU];
    __shared__ float sh_s[UU];
    __shared__ float sm_m[16], sm_s[16];
    __shared__ __align__(8) unsigned long long sm_mbar[2];
    float* red = (float*)(dsm + RED_OFF);      // 1024 floats

    const unsigned mbar0 = (unsigned)__cvta_generic_to_shared(&sm_mbar[0]);
    const unsigned mbar1 = (unsigned)__cvta_generic_to_shared(&sm_mbar[1]);

    if (tid == 0) {
        asm volatile("mbarrier.init.shared.b64 [%0], 1;" :: "r"(mbar0) : "memory");
        asm volatile("mbarrier.init.shared.b64 [%0], 1;" :: "r"(mbar1) : "memory");
        asm volatile("fence.proxy.async.shared::cta;" ::: "memory");
    }
    __syncthreads();

    unsigned par0 = 0, par1 = 0;   // mbarrier phase parity (per thread, uniform)
    float c_reg = 0.0f;            // cell state (threads 0..255)
    unsigned ph = *((volatile unsigned*)&d_bar[bid]);

    for (int k = 0; k <= 514; k++) {
        const int t = k - 2 * L;                // this layer's step (L2 lags 2)
        const bool attnAct = (t >= 0) && (t < TT);
        const bool gateAct = (t >= 1) && (t <= TT);

        if (k) gbar(ph);   // B0: Z of previous iteration complete
                           // (also 2-deep: L1's o1 writes are covered for L2)

        // ---- prologue: stage te-blocks 0 and 1 (hidden by phases A/1) ----
        if (attnAct && tid == 0) {
            mbar_expect_tx(mbar0, STAGE_BYTES);
            bulk_g2s(smemBase,          encG, 16384, mbar0);
            bulk_g2s(smemBase + 16384,  spG,  32768, mbar0);
            mbar_expect_tx(mbar1, STAGE_BYTES);
            bulk_g2s(smemBase + STAGE_BYTES,         encG + 16384, 16384, mbar1);
            bulk_g2s(smemBase + STAGE_BYTES + 16384, spG + 32768,  32768, mbar1);
        }

        // ---------------- phase A: gates -> h_{t-1} ------------------------
        if (tid < UU) {
            if (gateAct) {
                const float* Zb = Zl + b * GG;
                float zi = bz[tid]       + __ldcg(Zb + tid);
                float zf = bz[tid + 256] + __ldcg(Zb + tid + 256);
                float zg = bz[tid + 512] + __ldcg(Zb + tid + 512);
                float zo = bz[tid + 768] + __ldcg(Zb + tid + 768);
                float ig = 1.0f / (1.0f + expf(-zi));
                float fg = 1.0f / (1.0f + expf(-zf));
                float og = 1.0f / (1.0f + expf(-zo));
                c_reg = fg * c_reg + ig * tanhf(zg);
                float h = og * tanhf(c_reg);
                sh_h[tid] = h;
                __stcg(vT + (768 + tid) * BB + b, h);
                __stcg(outbuf + ((size_t)b * TT + (t - 1)) * UU + tid, h);
            } else if (attnAct) {   // t == 0 init
                c_reg = 0.0f;
                sh_h[tid] = 0.0f;
                __stcg(vT + (768 + tid) * BB + b, 0.0f);
            }
        }
        __syncthreads();   // sh_h ready for phase 1 (replaces old B1)

        if (attnAct) {
            // ---- x_t (layer2: norm of layer1's h_t, two iters back) -------
            float xv = 0.0f;
            if (tid < UU) {
                xv = (L == 0) ? d_secrets[((size_t)b * TT + t) * UU + tid]
                              : __ldcg(d_o1 + ((size_t)b * TT + t) * UU + tid);
            }
            if (L == 1) {   // uniform per CTA -> syncthreads legal
                red[tid]       = (tid < UU) ? xv : 0.0f;
                red[512 + tid] = (tid < UU) ? xv * xv : 0.0f;
                __syncthreads();
                for (int o = 256; o > 0; o >>= 1) {
                    if (tid < o) {
                        red[tid] += red[tid + o];
                        red[512 + tid] += red[512 + tid + o];
                    }
                    __syncthreads();
                }
                const float mean = red[0] * (1.0f / 256.0f);
                const float var  = red[512] * (1.0f / 256.0f) - mean * mean;
                const float sc = rsqrtf(var + 1e-4f);
                xv = (xv - mean) * sc;
                __syncthreads();
            }
            if (tid < UU) __stcg(vT + tid * BB + b, xv);

            // ---- phase 1: s = h @ Wa + Wa_b -------------------------------
            {
                const int uu = tid & 255, half = tid >> 8;
                float acc = 0.0f;
                const float* wp = WaW + (size_t)(half * 128) * UU + uu;
#pragma unroll 8
                for (int kk = 0; kk < 128; kk++)
                    acc += sh_h[half * 128 + kk] * wp[(size_t)kk * UU];
                red[tid] = acc;
                __syncthreads();
                if (tid < UU) sh_s[tid] = red[tid] + red[tid + 256] + Wab[tid];
                __syncthreads();
            }

            // ---- FUSED phases 2-4: TMA-staged online softmax + ctx --------
            {
                float va_r[8];
                __half2 s2[4];
#pragma unroll
                for (int j = 0; j < 8; j++) va_r[j] = vaW[lane * 8 + j];
#pragma unroll
                for (int p = 0; p < 4; p++)
                    s2[p] = __floats2half2_rn(sh_s[lane * 8 + 2 * p],
                                              sh_s[lane * 8 + 2 * p + 1]);

                float m = -1e30f, s = 0.0f;
                float acc[16];
#pragma unroll
                for (int i = 0; i < 16; i++) acc[i] = 0.0f;

                const int r0 = warp * 2, r1 = r0 + 1;

#pragma unroll 1
                for (int blk = 0; blk < 32; blk++) {
                    const int cur = blk & 1;
                    // wait for this block's fill
                    if (cur == 0) { mbar_wait(mbar0, par0); par0 ^= 1; }
                    else          { mbar_wait(mbar1, par1); par1 ^= 1; }

                    const uint4* eP = (const uint4*)(dsm + cur * STAGE_BYTES);
                    const uint4* sP = (const uint4*)(dsm + cur * STAGE_BYTES + 16384);
                    uint4 e0  = eP[r0 * 32 + lane];
                    uint4 e1  = eP[r1 * 32 + lane];
                    uint4 sA0 = sP[r0 * 64 + lane];
                    uint4 sB0 = sP[r0 * 64 + 32 + lane];
                    uint4 sA1 = sP[r1 * 64 + lane];
                    uint4 sB1 = sP[r1 * 64 + 32 + lane];

                    float l0 = 0.f, l1 = 0.f;
                    {
                        const __half2* h0 = reinterpret_cast<const __half2*>(&e0);
                        const __half2* h1 = reinterpret_cast<const __half2*>(&e1);
#pragma unroll
                        for (int pp = 0; pp < 4; pp++) {
                            float2 f0 = __half22float2(tanh2(__hadd2(s2[pp], h0[pp])));
                            float2 f1 = __half22float2(tanh2(__hadd2(s2[pp], h1[pp])));
                            l0 += va_r[2 * pp] * f0.x + va_r[2 * pp + 1] * f0.y;
                            l1 += va_r[2 * pp] * f1.x + va_r[2 * pp + 1] * f1.y;
                        }
                    }
#pragma unroll
                    for (int o = 16; o; o >>= 1) {
                        l0 += __shfl_xor_sync(0xffffffffu, l0, o);
                        l1 += __shfl_xor_sync(0xffffffffu, l1, o);
                    }

                    // row r0 (warp-uniform branch)
                    if (l0 > m) {
                        const float corr = __expf(m - l0);
                        m = l0;
                        s *= corr;
#pragma unroll
                        for (int i = 0; i < 16; i++) acc[i] *= corr;
                    }
                    {
                        const float w = __expf(l0 - m);
                        s += w;
                        const __half2* hA = reinterpret_cast<const __half2*>(&sA0);
                        const __half2* hB = reinterpret_cast<const __half2*>(&sB0);
#pragma unroll
                        for (int pp = 0; pp < 4; pp++) {
                            float2 fa = __half22float2(hA[pp]);
                            float2 fb = __half22float2(hB[pp]);
                            acc[2 * pp]         += w * fa.x;
                            acc[2 * pp + 1]     += w * fa.y;
                            acc[8 + 2 * pp]     += w * fb.x;
                            acc[8 + 2 * pp + 1] += w * fb.y;
                        }
                    }
                    // row r1
                    if (l1 > m) {
                        const float corr = __expf(m - l1);
                        m = l1;
                        s *= corr;
#pragma unroll
                        for (int i = 0; i < 16; i++) acc[i] *= corr;
                    }
                    {
                        const float w = __expf(l1 - m);
                        s += w;
                        const __half2* hA = reinterpret_cast<const __half2*>(&sA1);
                        const __half2* hB = reinterpret_cast<const __half2*>(&sB1);
#pragma unroll
                        for (int pp = 0; pp < 4; pp++) {
                            float2 fa = __half22float2(hA[pp]);
                            float2 fb = __half22float2(hB[pp]);
                            acc[2 * pp]         += w * fa.x;
                            acc[2 * pp + 1]     += w * fa.y;
                            acc[8 + 2 * pp]     += w * fb.x;
                            acc[8 + 2 * pp + 1] += w * fb.y;
                        }
                    }

                    __syncthreads();   // everyone done reading stage cur
                    // refill buffer cur with block blk+2 (distance-2)
                    if (tid == 0 && blk + 2 < 32) {
                        const unsigned st = smemBase + cur * STAGE_BYTES;
                        const unsigned mb = cur ? mbar1 : mbar0;
                        mbar_expect_tx(mb, STAGE_BYTES);
                        bulk_g2s(st,         encG + (size_t)(blk + 2) * 16384, 16384, mb);
                        bulk_g2s(st + 16384, spG  + (size_t)(blk + 2) * 32768, 32768, mb);
                    }
                }

                // ---- exact 16-way flash merge across warps ----------------
                if (lane == 0) { sm_m[warp] = m; sm_s[warp] = s; }
                __syncthreads();
                float M = sm_m[0];
#pragma unroll
                for (int w2 = 1; w2 < 16; w2++) M = fmaxf(M, sm_m[w2]);
                float S = 0.0f;
#pragma unroll
                for (int w2 = 0; w2 < 16; w2++)
                    S += sm_s[w2] * __expf(sm_m[w2] - M);
                const float fw = __expf(m - M);
                const float invS = 1.0f / S;
                float* buf = (float*)dsm;      // [16][512]
                {
                    float4 v0 = make_float4(acc[0] * fw, acc[1] * fw,
                                            acc[2] * fw, acc[3] * fw);
                    float4 v1 = make_float4(acc[4] * fw, acc[5] * fw,
                                            acc[6] * fw, acc[7] * fw);
                    float4 v2 = make_float4(acc[8] * fw, acc[9] * fw,
                                            acc[10] * fw, acc[11] * fw);
                    float4 v3 = make_float4(acc[12] * fw, acc[13] * fw,
                                            acc[14] * fw, acc[15] * fw);
                    float4* bp = reinterpret_cast<float4*>(buf + warp * 512);
                    bp[lane * 2]           = v0;
                    bp[lane * 2 + 1]       = v1;
                    bp[64 + lane * 2]      = v2;
                    bp[64 + lane * 2 + 1]  = v3;
                }
                __syncthreads();
                float ctx = 0.0f;
#pragma unroll
                for (int w2 = 0; w2 < 16; w2++)
                    ctx += buf[w2 * 512 + tid];
                __stcg(vT + (256 + tid) * BB + b, ctx * invS);
            }
        }

        gbar(ph);          // B2: v (all batches, this layer) visible

        // ---------------- phase D: Z[:, 16 cols] = v @ [K;R] ----------------
        if (attnAct) {
            float (*vsh)[68] = reinterpret_cast<float(*)[68]>((float*)dsm);
            float (*wsh)[20] = reinterpret_cast<float(*)[20]>((float*)dsm + 64 * 68);
            const int c0 = b * 16;
            const int rg = tid & 7, cg = (tid >> 3) & 3, bg = tid >> 5;
            float acc[4][4] = {};

            for (int tile = 0; tile < 16; tile++) {
                const int rbase = tile * 64;
#pragma unroll
                for (int i = 0; i < 2; i++) {
                    const int e4i = i * 512 + tid;
                    const int r = e4i >> 4, b4 = e4i & 15;
                    float4 vv = __ldcg(
                        reinterpret_cast<const float4*>(vT + (size_t)(rbase + r) * BB) + b4);
                    *reinterpret_cast<float4*>(&vsh[r][b4 * 4]) = vv;
                }
                if (tid < 256) {
                    const int r = tid >> 2, c4 = tid & 3;
                    const int gr = rbase + r;
                    const float* Wrow = (gr < 768) ? (Kw + (size_t)gr * GG)
                                                   : (Rw + (size_t)(gr - 768) * GG);
                    *reinterpret_cast<float4*>(&wsh[r][c4 * 4]) =
                        *reinterpret_cast<const float4*>(Wrow + c0 + c4 * 4);
                }
                __syncthreads();
#pragma unroll
                for (int rr = 0; rr < 8; rr++) {
                    const int r = rr * 8 + rg;
                    float4 vv = *reinterpret_cast<const float4*>(&vsh[r][bg * 4]);
                    float4 ww = *reinterpret_cast<const float4*>(&wsh[r][cg * 4]);
                    const float vvv[4] = {vv.x, vv.y, vv.z, vv.w};
                    const float www[4] = {ww.x, ww.y, ww.z, ww.w};
#pragma unroll
                    for (int i = 0; i < 4; i++)
#pragma unroll
                        for (int j = 0; j < 4; j++)
                            acc[i][j] += vvv[i] * www[j];
                }
                __syncthreads();
            }
            // reduce over rg (lane bits 0..2)
#pragma unroll
            for (int i = 0; i < 4; i++)
#pragma unroll
                for (int j = 0; j < 4; j++) {
                    float a = acc[i][j];
                    a += __shfl_xor_sync(0xffffffffu, a, 1);
                    a += __shfl_xor_sync(0xffffffffu, a, 2);
                    a += __shfl_xor_sync(0xffffffffu, a, 4);
                    acc[i][j] = a;
                }
            if (rg == 0) {
#pragma unroll
                for (int i = 0; i < 4; i++)
#pragma unroll
                    for (int j = 0; j < 4; j++)
                        __stcg(Zl + (size_t)(bg * 4 + i) * GG + c0 + cg * 4 + j, acc[i][j]);
            }
        }
    }
}

// ---------------------------------------------------------------------------
// fp32 -> fp16 bulk convert, 8 elems/thread.
// ---------------------------------------------------------------------------
__global__ __launch_bounds__(256) void f2h_kernel(
    const float* __restrict__ in, __half* __restrict__ out, int n8)
{
    const int i = blockIdx.x * blockDim.x + threadIdx.x;
    if (i >= n8) return;
    const float4* p = reinterpret_cast<const float4*>(in) + 2 * i;
    float4 a = p[0], c = p[1];
    __half2 h0 = __floats2half2_rn(a.x, a.y);
    __half2 h1 = __floats2half2_rn(a.z, a.w);
    __half2 h2 = __floats2half2_rn(c.x, c.y);
    __half2 h3 = __floats2half2_rn(c.z, c.w);
    uint4 q;
    q.x = *reinterpret_cast<unsigned*>(&h0);
    q.y = *reinterpret_cast<unsigned*>(&h1);
    q.z = *reinterpret_cast<unsigned*>(&h2);
    q.w = *reinterpret_cast<unsigned*>(&h3);
    reinterpret_cast<uint4*>(out)[i] = q;
}

// ---------------------------------------------------------------------------
// Generic tiled SGEMM: C[M,N] = A[M,K] @ B[K,N] + bias[N], OutT in {float,half}
// ---------------------------------------------------------------------------
__device__ __forceinline__ void store_out(float* p, float v) { *p = v; }
__device__ __forceinline__ void store_out(__half* p, float v) {
    *p = __float2half_rn(v);
}

template <typename OutT>
__global__ __launch_bounds__(128) void gemm_kernel(
    const float* __restrict__ A, const float* __restrict__ Bm,
    const float* __restrict__ bias, OutT* __restrict__ C,
    int M, int K, int N)
{
    __shared__ __align__(16) float As[16][68];
    __shared__ __align__(16) float Bs[16][64];
    const int m0 = blockIdx.x * 64;
    const int n0 = blockIdx.y * 64;
    const int tid = threadIdx.x;
    const int tx = tid & 15, ty = tid >> 4;

    float acc[8][4] = {};

    for (int k0 = 0; k0 < K; k0 += 16) {
#pragma unroll
        for (int i = 0; i < 8; i++) {
            const int e = i * 128 + tid;
            const int m = e >> 4, kk = e & 15;
            As[kk][m] = A[(size_t)(m0 + m) * K + k0 + kk];
        }
#pragma unroll
        for (int i = 0; i < 8; i++) {
            const int e = i * 128 + tid;
            const int kk = e >> 6, nn = e & 63;
            Bs[kk][nn] = Bm[(size_t)(k0 + kk) * N + n0 + nn];
        }
        __syncthreads();
#pragma unroll
        for (int kk = 0; kk < 16; kk++) {
            float4 b4  = *reinterpret_cast<const float4*>(&Bs[kk][tx * 4]);
            float4 alo = *reinterpret_cast<const float4*>(&As[kk][ty * 8]);
            float4 ahi = *reinterpret_cast<const float4*>(&As[kk][ty * 8 + 4]);
            const float a[8] = {alo.x, alo.y, alo.z, alo.w, ahi.x, ahi.y, ahi.z, ahi.w};
            const float bb[4] = {b4.x, b4.y, b4.z, b4.w};
#pragma unroll
            for (int q = 0; q < 8; q++)
#pragma unroll
                for (int j = 0; j < 4; j++)
                    acc[q][j] += a[q] * bb[j];
        }
        __syncthreads();
    }
#pragma unroll
    for (int q = 0; q < 8; q++) {
        const int m = m0 + ty * 8 + q;
#pragma unroll
        for (int j = 0; j < 4; j++) {
            const int n = n0 + tx * 4 + j;
            store_out(&C[(size_t)m * N + n], acc[q][j] + bias[n]);
        }
    }
}

// whatever_norm over last dim (256), in-place. grid = rows, block = 256.
__global__ __launch_bounds__(256) void norm_kernel(float* __restrict__ x)
{
    __shared__ float rs[256], rq[256];
    const int row = blockIdx.x, tid = threadIdx.x;
    const float v = x[(size_t)row * UU + tid];
    rs[tid] = v;
    rq[tid] = v * v;
    __syncthreads();
    for (int o = 128; o > 0; o >>= 1) {
        if (tid < o) { rs[tid] += rs[tid + o]; rq[tid] += rq[tid + o]; }
        __syncthreads();
    }
    const float mean = rs[0] * (1.0f / 256.0f);
    const float var = rq[0] * (1.0f / 256.0f) - mean * mean;
    const float sc = rsqrtf(var + 1e-4f);
    x[(size_t)row * UU + tid] = (v - mean) * sc;
}

// Row softmax over NC=64. block = 256 (8 warps -> 8 rows), grid = rows/8.
__global__ __launch_bounds__(256) void softmax_kernel(
    const float* __restrict__ in, float* __restrict__ outp)
{
    const int warp = threadIdx.x >> 5, lane = threadIdx.x & 31;
    const int row = blockIdx.x * 8 + warp;
    const float* p = in + (size_t)row * NC;
    float a = p[lane], b = p[lane + 32];
    float m = fmaxf(a, b);
#pragma unroll
    for (int o = 16; o; o >>= 1) m = fmaxf(m, __shfl_xor_sync(0xffffffffu, m, o));
    const float ea = expf(a - m), eb = expf(b - m);
    float s = ea + eb;
#pragma unroll
    for (int o = 16; o; o >>= 1) s += __shfl_xor_sync(0xffffffffu, s, o);
    const float inv = 1.0f / s;
    outp[(size_t)row * NC + lane] = ea * inv;
    outp[(size_t)row * NC + lane + 32] = eb * inv;
}

// ---------------------------------------------------------------------------
extern "C" void kernel_launch(void* const* d_in, const int* in_sizes, int n_in,
                              void* d_out, int out_size)
{
    const float* trans  = (const float*)d_in[0];
    const float* speech = (const float*)d_in[1];
    const float* embW   = (const float*)d_in[2];
    const float* embb   = (const float*)d_in[3];
    const float* Ua1W = (const float*)d_in[4];
    const float* Ua1b = (const float*)d_in[5];
    const float* Wa1W = (const float*)d_in[6];
    const float* Wa1b = (const float*)d_in[7];
    const float* va1W = (const float*)d_in[8];
    const float* va1b = (const float*)d_in[9];
    const float* K1   = (const float*)d_in[10];
    const float* R1   = (const float*)d_in[11];
    const float* b1   = (const float*)d_in[12];
    const float* Ua2W = (const float*)d_in[13];
    const float* Ua2b = (const float*)d_in[14];
    const float* Wa2W = (const float*)d_in[15];
    const float* Wa2b = (const float*)d_in[16];
    const float* va2W = (const float*)d_in[17];
    const float* va2b = (const float*)d_in[18];
    const float* K2   = (const float*)d_in[19];
    const float* R2   = (const float*)d_in[20];
    const float* b2   = (const float*)d_in[21];
    const float* m1W  = (const float*)d_in[22];
    const float* m1b  = (const float*)d_in[23];
    const float* m2W  = (const float*)d_in[24];
    const float* m2b  = (const float*)d_in[25];
    const float* dW   = (const float*)d_in[26];
    const float* db   = (const float*)d_in[27];

    float *secrets, *o2, *m1o, *m2o, *lg;
    __half *enc1h, *enc2h, *speechh;
    cudaGetSymbolAddress((void**)&secrets, d_secrets);
    cudaGetSymbolAddress((void**)&enc1h, d_enc1h);
    cudaGetSymbolAddress((void**)&enc2h, d_enc2h);
    cudaGetSymbolAddress((void**)&speechh, d_speechh);
    cudaGetSymbolAddress((void**)&o2, d_o2);
    cudaGetSymbolAddress((void**)&m1o, d_m1o);
    cudaGetSymbolAddress((void**)&m2o, d_m2o);
    cudaGetSymbolAddress((void**)&lg, d_lg);

    const int ROWS = BB * TT;      // 32768
    const int EROWS = BB * TE;     // 65536

    // One-time projections (enc written directly as fp16) + speech conversion
    gemm_kernel<<<dim3(ROWS / 64, UU / 64), 128>>>(trans, embW, embb, secrets, ROWS, NC, UU);
    gemm_kernel<<<dim3(EROWS / 64, UU / 64), 128>>>(speech, Ua1W, Ua1b, enc1h, EROWS, EE, UU);
    gemm_kernel<<<dim3(EROWS / 64, UU / 64), 128>>>(speech, Ua2W, Ua2b, enc2h, EROWS, EE, UU);
    {
        const int n8 = BB * TE * EE / 8;
        f2h_kernel<<<(n8 + 255) / 256, 256>>>(speech, speechh, n8);
    }

    // Both recurrent layers, pipelined (depth 2), in ONE persistent kernel
    cudaFuncSetAttribute(decoder_persistent,
                         cudaFuncAttributeMaxDynamicSharedMemorySize, DSM_BYTES);
    decoder_persistent<<<128, 512, DSM_BYTES>>>(
        Wa1W, Wa1b, va1W, va1b, K1, R1, b1,
        Wa2W, Wa2b, va2W, va2b, K2, R2, b2);

    // MLP head
    norm_kernel<<<ROWS, 256>>>(o2);
    gemm_kernel<<<dim3(ROWS / 64, UU / 64), 128>>>(o2, m1W, m1b, m1o, ROWS, UU, UU);
    norm_kernel<<<ROWS, 256>>>(m1o);
    gemm_kernel<<<dim3(ROWS / 64, UU / 64), 128>>>(m1o, m2W, m2b, m2o, ROWS, UU, UU);
    norm_kernel<<<ROWS, 256>>>(m2o);
    gemm_kernel<<<dim3(ROWS / 64, NC / 64), 128>>>(m2o, dW, db, lg, ROWS, UU, NC);
    softmax_kernel<<<ROWS / 8, 256>>>(lg, (float*)d_out);

    (void)in_sizes; (void)n_in; (void)out_size;
}